// round 11
// baseline (speedup 1.0000x reference)
#include <cuda_runtime.h>
#include <cuda_fp16.h>
#include <cstdint>
#include <cstddef>

#define EPS   1e-6f
#define B_    16
#define NN    1024
#define FDIM  64
#define OUTD  128
#define KC    32
#define NITER (NN / KC)

// strides in b32 units (bank-conflict-free: 20*lr+lc and 100*lr+lc distinct mod 32)
#define SA_STRH 20      // A stage: 128 rows x 80 B
#define SB_STRH 20      // B stage: 128 f-rows x 80 B
#define OC_STRH 100     // ocat: 128 rows x 400 B (192 fp16 + pad)
#define KM_STRH 100     // KmatT: 128 n-rows x 400 B (192 fp16 + pad)

// smem layout (bytes)
#define OFF_ADIAG 0
#define OFF_INV   512
#define OFF_SROW  1024
#define OFF_DYN   1536
#define ASTG_B    (128 * SA_STRH * 4)          // 10240
#define BSTG_B    (128 * SB_STRH * 4)          // 10240
#define STG_B     (ASTG_B + BSTG_B)            // 20480
#define OFF_STAGE(s) (OFF_DYN + (s) * STG_B)
#define OFF_OC    OFF_DYN                      // 51200 B (inside 3 stages = 61440)
#define OFF_KM    (OFF_DYN + 3 * STG_B)        // 62976
#define SMEM_BYTES (OFF_KM + 128 * KM_STRH * 4)  // 114176

__device__ float  g_inv[B_ * NN];
__device__ float  g_s[B_ * NN];
__device__ __half g_Bh[(size_t)B_ * 128 * NN];   // [b][f:128][k:1024] fp16; f>=64 = s*x

__device__ __forceinline__ uint32_t smem_u32(const void* p) {
    uint32_t a;
    asm("{ .reg .u64 t; cvta.to.shared.u64 t, %1; cvt.u32.u64 %0, t; }"
        : "=r"(a) : "l"(p));
    return a;
}
__device__ __forceinline__ void cp_async16(uint32_t saddr, const void* g) {
    asm volatile("cp.async.cg.shared.global [%0], [%1], 16;"
                 :: "r"(saddr), "l"(g) : "memory");
}
#define CP_COMMIT() asm volatile("cp.async.commit_group;" ::: "memory")
#define CP_WAIT0()  asm volatile("cp.async.wait_group 0;" ::: "memory")
#define MEMBAR_CTA() asm volatile("membar.cta;" ::: "memory")
__device__ __forceinline__ void bar_sync512(int id) {
    asm volatile("bar.sync %0, 512;" :: "r"(id) : "memory");
}
__device__ __forceinline__ void bar_arrive512(int id) {
    asm volatile("bar.arrive %0, 512;" :: "r"(id) : "memory");
}
__device__ __forceinline__ void bar_sync_n(int id, int n) {
    asm volatile("bar.sync %0, %1;" :: "r"(id), "r"(n) : "memory");
}
__device__ __forceinline__ uint32_t h2pack(float lo, float hi) {
    __half2 h = __floats2half2_rn(lo, hi);
    return *(uint32_t*)&h;
}
__device__ __forceinline__ float h2f_rn(float v) {
    return __half2float(__float2half_rn(v));
}
__device__ __forceinline__ void mma_f16(float* c, const uint32_t* a, const uint32_t* b) {
    asm volatile(
        "mma.sync.aligned.m16n8k16.row.col.f32.f16.f16.f32 "
        "{%0,%1,%2,%3}, {%4,%5,%6,%7}, {%8,%9}, {%0,%1,%2,%3};"
        : "+f"(c[0]), "+f"(c[1]), "+f"(c[2]), "+f"(c[3])
        : "r"(a[0]), "r"(a[1]), "r"(a[2]), "r"(a[3]), "r"(b[0]), "r"(b[1]));
}

// ---------------------------------------------------------------------------
// Kernel 1: degree scalars. deg[b,i] = rowsum(A) - A[i,i] + 1
// ---------------------------------------------------------------------------
__global__ void deg_kernel(const float* __restrict__ A) {
    int warp = (blockIdx.x * blockDim.x + threadIdx.x) >> 5;
    int lane = threadIdx.x & 31;
    if (warp >= B_ * NN) return;
    const float* row = A + (size_t)warp * NN;
    float sum = 0.f;
    const float4* r4 = (const float4*)row;
#pragma unroll
    for (int w = 0; w < 8; w++) {
        float4 v = r4[w * 32 + lane];
        sum += v.x + v.y + v.z + v.w;
    }
#pragma unroll
    for (int off = 16; off > 0; off >>= 1)
        sum += __shfl_down_sync(0xFFFFFFFFu, sum, off);
    if (lane == 0) {
        float deg = sum - row[warp % NN] + 1.0f;
        g_inv[warp] = 1.0f / (EPS + deg);
        g_s[warp]   = 1.0f / (EPS + sqrtf(deg));
    }
}

// ---------------------------------------------------------------------------
// Kernel 2: transpose+convert: g_Bh[b][f][k] = fp16(x[k][f]) / fp16(s_k*x[k][f-64])
// One block per (k-tile of 128, batch).
// ---------------------------------------------------------------------------
__global__ __launch_bounds__(256, 4)
void prep_kernel(const float* __restrict__ x) {
    __shared__ float xt[128][65];
    __shared__ float sk[128];
    const int b = blockIdx.y, k0 = blockIdx.x * 128;
    const int tid = threadIdx.x;
    const float* xb = x + ((size_t)b * NN + k0) * FDIM;
#pragma unroll
    for (int q = 0; q < 8; q++) {
        int e = tid + q * 256;            // 2048 float4
        int row = e >> 4, c4 = (e & 15) * 4;
        float4 v = *(const float4*)&xb[(size_t)row * FDIM + c4];
        xt[row][c4] = v.x; xt[row][c4 + 1] = v.y;
        xt[row][c4 + 2] = v.z; xt[row][c4 + 3] = v.w;
    }
    if (tid < 128) sk[tid] = g_s[b * NN + k0 + tid];
    __syncthreads();
    uint32_t* dst = (uint32_t*)(g_Bh + (size_t)b * 128 * NN + k0);
#pragma unroll
    for (int q = 0; q < 32; q++) {
        int e = tid + q * 256;            // 8192 half2
        int f = e >> 6, kp = e & 63;
        float v0, v1;
        if (f < 64) {
            v0 = xt[2 * kp][f];
            v1 = xt[2 * kp + 1][f];
        } else {
            v0 = sk[2 * kp] * xt[2 * kp][f - 64];
            v1 = sk[2 * kp + 1] * xt[2 * kp + 1][f - 64];
        }
        dst[(size_t)f * (NN / 2) + kp] = h2pack(v0, v1);
    }
}

// ---------------------------------------------------------------------------
// Kernel 3: fused, warp-specialized fp16 MMA. Warps 0-7 consumers (64x32),
// warps 8-15 producers. R9 barrier protocol (immediate arrive).
// ---------------------------------------------------------------------------
__global__ __launch_bounds__(512, 1)
void fused_mma_kernel(const float* __restrict__ A, const float* __restrict__ x,
                      const float* __restrict__ Kmat, const float* __restrict__ bias,
                      float* __restrict__ out) {
    extern __shared__ char smc[];
    float* smf = (float*)smc;
    const uint32_t sb = smem_u32(smc);
    const int tid  = threadIdx.x;
    const int wid  = tid >> 5;
    const int lane = tid & 31;
    const int b    = blockIdx.y;
    const int row0 = blockIdx.x * 128;
    const int lr = lane >> 2;
    const int lc = lane & 3;

    const float* Ab = A + (size_t)b * NN * NN;
    const float* xb = x + (size_t)b * NN * FDIM;
    const __half* Bb = g_Bh + (size_t)b * 128 * NN;

    if (wid >= 8) {
        // ---------------- PRODUCER ----------------
        const int ptid = tid - 256;
        const int arow = ptid >> 3;              // 0..31 (+32q)
        const int acol = (ptid & 7) * 4;         // fp32 col in k-tile
        const int bf   = ptid >> 1;              // 0..127 (f row of B tile)
        const int bch  = (ptid & 1) * 2;         // chunk base (2 x 16B per thread)
        const float* gA = Ab + (size_t)(row0 + arow) * NN + acol;
        const __half* gB = Bb + (size_t)bf * NN;

        if (ptid < 128) {
            int grow = row0 + ptid;
            smf[(OFF_ADIAG >> 2) + ptid] = h2f_rn(__ldg(&Ab[(size_t)grow * NN + grow]));
            smf[(OFF_INV >> 2) + ptid]   = g_inv[b * NN + grow];
            smf[(OFF_SROW >> 2) + ptid]  = g_s[b * NN + grow];
        }

        for (int it = 0; it < NITER; ++it) {
            const int s = it % 3;
            const int k0 = it * KC;
            if (it >= 3) bar_sync512(4 + s);
            // A: LDG fp32
            float4 va[4];
#pragma unroll
            for (int q = 0; q < 4; q++)
                va[q] = *(const float4*)(gA + k0 + (size_t)q * 32 * NN);
            // B: raw cp.async of fp16 (64 B per f row = 4 chunks; 2 per thread)
            uint32_t sBb = sb + OFF_STAGE(s) + ASTG_B;
#pragma unroll
            for (int q = 0; q < 2; q++)
                cp_async16(sBb + bf * 80 + (bch + q) * 16,
                           gB + k0 + (bch + q) * 8);
            CP_COMMIT();
            // A: cvt fp32->fp16x2, STS 8B
            char* dA = smc + OFF_STAGE(s);
#pragma unroll
            for (int q = 0; q < 4; q++) {
                uint2 w;
                w.x = h2pack(va[q].x, va[q].y);
                w.y = h2pack(va[q].z, va[q].w);
                *(uint2*)(dA + (arow + 32 * q) * 80 + acol * 2) = w;
            }
            CP_WAIT0();
            MEMBAR_CTA();
            bar_arrive512(1 + s);
        }
        // stage KmatT fp16 [n:128][k:192] while consumers drain the tail
        {
            uint32_t* km = (uint32_t*)(smc + OFF_KM);
#pragma unroll
            for (int e = ptid; e < 128 * 96; e += 256) {
                int n = e >> 6 << 0;  // placeholder
                n = e / 96;
                int kp = e - n * 96;
                float v0 = __ldg(&Kmat[(size_t)(2 * kp) * 128 + n]);
                float v1 = __ldg(&Kmat[(size_t)(2 * kp + 1) * 128 + n]);
                km[n * KM_STRH + kp] = h2pack(v0, v1);
            }
        }
    } else {
        // ---------------- CONSUMER ----------------
        const int m_base = (wid >> 2) * 64;
        const int n_base = (wid & 3) * 32;
        const bool scaled = (n_base >= 64);
        const int f_base = scaled ? n_base - 64 : n_base;

        float acc[4][4][4];
#pragma unroll
        for (int mt = 0; mt < 4; mt++)
#pragma unroll
            for (int nt = 0; nt < 4; nt++)
#pragma unroll
                for (int q = 0; q < 4; q++) acc[mt][nt][q] = 0.f;

        for (int it = 0; it < NITER; ++it) {
            const int s = it % 3;
            bar_sync512(1 + s);
            const uint32_t* sA = (const uint32_t*)(smc + OFF_STAGE(s));
            const uint32_t* sB = (const uint32_t*)(smc + OFF_STAGE(s) + ASTG_B);
#pragma unroll
            for (int ks = 0; ks < 2; ks++) {      // 2 x k16 per 32-k tile
                const int kb = ks * 8;
                uint32_t af[4][4], bf2[4][2];
#pragma unroll
                for (int mt = 0; mt < 4; mt++) {
                    const uint32_t* p = sA + (m_base + mt * 16 + lr) * SA_STRH + kb + lc;
                    af[mt][0] = p[0];
                    af[mt][1] = p[8 * SA_STRH];
                    af[mt][2] = p[4];
                    af[mt][3] = p[8 * SA_STRH + 4];
                }
#pragma unroll
                for (int nt = 0; nt < 4; nt++) {
                    const uint32_t* p = sB + (n_base + nt * 8 + lr) * SB_STRH + kb + lc;
                    bf2[nt][0] = p[0];
                    bf2[nt][1] = p[4];
                }
#pragma unroll
                for (int mt = 0; mt < 4; mt++)
#pragma unroll
                    for (int nt = 0; nt < 4; nt++)
                        mma_f16(acc[mt][nt], af[mt], bf2[nt]);
            }
            bar_arrive512(4 + s);
        }
        bar_sync_n(7, 256);

        // epilogue 1: analytic diagonal fix -> ocat fp16 [128][192] (stride 400B)
        uint32_t* oc = (uint32_t*)(smc + OFF_OC);
#pragma unroll
        for (int mt = 0; mt < 4; mt++) {
#pragma unroll
            for (int nt = 0; nt < 4; nt++) {
                const int f = f_base + nt * 8 + lc * 2;
#pragma unroll
                for (int h = 0; h < 2; h++) {
                    const int r = m_base + mt * 16 + lr + h * 8;
                    const float ad = smf[(OFF_ADIAG >> 2) + r];   // fp16-rounded
                    const float c0 = acc[mt][nt][h * 2 + 0];
                    const float c1 = acc[mt][nt][h * 2 + 1];
                    float2 xv = *(const float2*)&xb[(size_t)(row0 + r) * FDIM + f];
                    if (!scaled) {
                        const float inv = smf[(OFF_INV >> 2) + r];
                        float xhx = h2f_rn(xv.x), xhy = h2f_rn(xv.y);
                        float o1a = c0 - ad * xhx;
                        float o1b = c1 - ad * xhy;
                        oc[r * OC_STRH + (f >> 1)] =
                            h2pack(o1a, o1b);
                        oc[r * OC_STRH + ((64 + f) >> 1)] =
                            h2pack(inv * (o1a + xv.x), inv * (o1b + xv.y));
                    } else {
                        const float sv = smf[(OFF_SROW >> 2) + r];
                        float sxx = h2f_rn(sv * xv.x), sxy = h2f_rn(sv * xv.y);
                        float o3a = sv * c0 - sv * ad * sxx + sv * sv * xv.x;
                        float o3b = sv * c1 - sv * ad * sxy + sv * sv * xv.y;
                        oc[r * OC_STRH + ((128 + f) >> 1)] = h2pack(o3a, o3b);
                    }
                }
            }
        }
    }
    __syncthreads();   // OC + KM ready; all 16 warps join

    // ---- GEMM2: out[128,128] = ocat[128,192] @ KmatT^T  (fp16, 12 k-steps)
    const int mm = (wid >> 2) * 32;
    const int n4 = (wid & 3) * 32;
    const uint32_t* ocp = (const uint32_t*)(smc + OFF_OC);
    const uint32_t* kmp = (const uint32_t*)(smc + OFF_KM);
    float acc2[2][4][4];
#pragma unroll
    for (int mt = 0; mt < 2; mt++)
#pragma unroll
        for (int nt = 0; nt < 4; nt++)
#pragma unroll
            for (int q = 0; q < 4; q++) acc2[mt][nt][q] = 0.f;

#pragma unroll
    for (int ks = 0; ks < 12; ks++) {
        const int kb = ks * 8;
        uint32_t af[2][4], bf2[4][2];
#pragma unroll
        for (int mt = 0; mt < 2; mt++) {
            const uint32_t* p = ocp + (mm + mt * 16 + lr) * OC_STRH + kb + lc;
            af[mt][0] = p[0];
            af[mt][1] = p[8 * OC_STRH];
            af[mt][2] = p[4];
            af[mt][3] = p[8 * OC_STRH + 4];
        }
#pragma unroll
        for (int nt = 0; nt < 4; nt++) {
            const uint32_t* p = kmp + (n4 + nt * 8 + lr) * KM_STRH + kb + lc;
            bf2[nt][0] = p[0];
            bf2[nt][1] = p[4];
        }
#pragma unroll
        for (int mt = 0; mt < 2; mt++)
#pragma unroll
            for (int nt = 0; nt < 4; nt++)
                mma_f16(acc2[mt][nt], af[mt], bf2[nt]);
    }

    // ---- bias + relu + store
#pragma unroll
    for (int mt = 0; mt < 2; mt++) {
#pragma unroll
        for (int nt = 0; nt < 4; nt++) {
            const int col = n4 + nt * 8 + lc * 2;
            float2 bv = *(const float2*)&bias[col];
#pragma unroll
            for (int h = 0; h < 2; h++) {
                const int r = mm + mt * 16 + lr + h * 8;
                float2 o;
                o.x = fmaxf(acc2[mt][nt][h * 2 + 0] + bv.x, 0.f);
                o.y = fmaxf(acc2[mt][nt][h * 2 + 1] + bv.y, 0.f);
                *(float2*)&out[((size_t)b * NN + row0 + r) * OUTD + col] = o;
            }
        }
    }
}

// ---------------------------------------------------------------------------
extern "C" void kernel_launch(void* const* d_in, const int* in_sizes, int n_in,
                              void* d_out, int out_size) {
    const float *x = nullptr, *A = nullptr, *Kmat = nullptr, *bias = nullptr;
    for (int i = 0; i < n_in; i++) {
        switch (in_sizes[i]) {
            case B_ * NN * FDIM:  x    = (const float*)d_in[i]; break;
            case B_ * NN * NN:    A    = (const float*)d_in[i]; break;
            case 3 * FDIM * OUTD: Kmat = (const float*)d_in[i]; break;
            case OUTD:            bias = (const float*)d_in[i]; break;
        }
    }
    float* out = (float*)d_out;

    static bool attr_set = false;
    if (!attr_set) {
        cudaFuncSetAttribute(fused_mma_kernel,
                             cudaFuncAttributeMaxDynamicSharedMemorySize, SMEM_BYTES);
        attr_set = true;
    }

    deg_kernel<<<(B_ * NN * 32 + 255) / 256, 256>>>(A);
    prep_kernel<<<dim3(NN / 128, B_), 256>>>(x);
    fused_mma_kernel<<<dim3(NN / 128, B_), 512, SMEM_BYTES>>>(A, x, Kmat, bias, out);
}

// round 12
// speedup vs baseline: 1.1113x; 1.1113x over previous
#include <cuda_runtime.h>
#include <cuda_fp16.h>
#include <cstdint>
#include <cstddef>

#define EPS   1e-6f
#define B_    16
#define NN    1024
#define FDIM  64
#define OUTD  128
#define KC    32
#define NITER (NN / KC)
#define NCTAS (8 * 16)

// strides in b32 units
#define SA_STRH 20
#define SB_STRH 20
#define OC_STRH 100
#define KM_STRH 100

// smem layout (bytes)
#define OFF_ADIAG 0
#define OFF_INV   512
#define OFF_SROW  1024
#define OFF_DYN   1536
#define ASTG_B    (128 * SA_STRH * 4)
#define BSTG_B    (128 * SB_STRH * 4)
#define STG_B     (ASTG_B + BSTG_B)
#define OFF_STAGE(s) (OFF_DYN + (s) * STG_B)
#define OFF_OC    OFF_DYN
#define OFF_KM    (OFF_DYN + 3 * STG_B)
#define SMEM_BYTES (OFF_KM + 128 * KM_STRH * 4)   // 114176

__device__ float  g_inv[B_ * NN];
__device__ float  g_s[B_ * NN];
__device__ __half g_Bh[(size_t)B_ * 128 * NN];
__device__ volatile unsigned g_bar[2];

__device__ __forceinline__ uint32_t smem_u32(const void* p) {
    uint32_t a;
    asm("{ .reg .u64 t; cvta.to.shared.u64 t, %1; cvt.u32.u64 %0, t; }"
        : "=r"(a) : "l"(p));
    return a;
}
__device__ __forceinline__ void cp_async16(uint32_t saddr, const void* g) {
    asm volatile("cp.async.cg.shared.global [%0], [%1], 16;"
                 :: "r"(saddr), "l"(g) : "memory");
}
#define CP_COMMIT() asm volatile("cp.async.commit_group;" ::: "memory")
#define CP_WAIT0()  asm volatile("cp.async.wait_group 0;" ::: "memory")
#define MEMBAR_CTA() asm volatile("membar.cta;" ::: "memory")
__device__ __forceinline__ void bar_sync512(int id) {
    asm volatile("bar.sync %0, 512;" :: "r"(id) : "memory");
}
__device__ __forceinline__ void bar_arrive512(int id) {
    asm volatile("bar.arrive %0, 512;" :: "r"(id) : "memory");
}
__device__ __forceinline__ void bar_sync_n(int id, int n) {
    asm volatile("bar.sync %0, %1;" :: "r"(id), "r"(n) : "memory");
}
__device__ __forceinline__ uint32_t h2pack(float lo, float hi) {
    __half2 h = __floats2half2_rn(lo, hi);
    return *(uint32_t*)&h;
}
__device__ __forceinline__ float h2f_rn(float v) {
    return __half2float(__float2half_rn(v));
}
__device__ __forceinline__ void mma_f16(float* c, const uint32_t* a, const uint32_t* b) {
    asm volatile(
        "mma.sync.aligned.m16n8k16.row.col.f32.f16.f16.f32 "
        "{%0,%1,%2,%3}, {%4,%5,%6,%7}, {%8,%9}, {%0,%1,%2,%3};"
        : "+f"(c[0]), "+f"(c[1]), "+f"(c[2]), "+f"(c[3])
        : "r"(a[0]), "r"(a[1]), "r"(a[2]), "r"(a[3]), "r"(b[0]), "r"(b[1]));
}
// grid-wide barrier: all NCTAS CTAs resident (128 CTAs, 1/SM, 148 SMs)
__device__ __forceinline__ void grid_sync(int i) {
    __syncthreads();
    if (threadIdx.x == 0) {
        __threadfence();
        atomicAdd((unsigned*)&g_bar[i], 1u);
        while (g_bar[i] < (unsigned)NCTAS)
            asm volatile("nanosleep.u32 128;");
        __threadfence();   // acquire: invalidate L1 before reading peers' data
    }
    __syncthreads();
}

__global__ void reset_kernel() { g_bar[0] = 0; g_bar[1] = 0; }

// ---------------------------------------------------------------------------
// Mega kernel: phase1 deg (own rows) -> sync -> phase1.5 B-build -> sync ->
// phase2 warp-specialized fp16 dual-GEMM + epilogue + GEMM2.
// ---------------------------------------------------------------------------
__global__ __launch_bounds__(512, 1)
void mega_kernel(const float* __restrict__ A, const float* __restrict__ x,
                 const float* __restrict__ Kmat, const float* __restrict__ bias,
                 float* __restrict__ out) {
    extern __shared__ char smc[];
    float* smf = (float*)smc;
    const uint32_t sb = smem_u32(smc);
    const int tid  = threadIdx.x;
    const int wid  = tid >> 5;
    const int lane = tid & 31;
    const int b    = blockIdx.y;
    const int row0 = blockIdx.x * 128;
    const int lr = lane >> 2;
    const int lc = lane & 3;

    const float* Ab = A + (size_t)b * NN * NN;
    const float* xb = x + (size_t)b * NN * FDIM;
    const __half* Bb = g_Bh + (size_t)b * 128 * NN;

    // ================= PHASE 1: degree scalars for own 128 rows =============
#pragma unroll 1
    for (int rr = 0; rr < 8; rr++) {
        const int lrow = wid * 8 + rr;
        const int grow = row0 + lrow;
        const float4* r4 = (const float4*)(Ab + (size_t)grow * NN);
        float sum = 0.f;
#pragma unroll
        for (int w = 0; w < 8; w++) {
            float4 v = r4[w * 32 + lane];
            sum += v.x + v.y + v.z + v.w;
        }
#pragma unroll
        for (int off = 16; off > 0; off >>= 1)
            sum += __shfl_down_sync(0xFFFFFFFFu, sum, off);
        if (lane == 0) {
            float ad  = Ab[(size_t)grow * NN + grow];
            float deg = sum - ad + 1.0f;
            float inv = 1.0f / (EPS + deg);
            float sv  = 1.0f / (EPS + sqrtf(deg));
            g_s[b * NN + grow]  = sv;
            smf[(OFF_ADIAG >> 2) + lrow] = h2f_rn(ad);
            smf[(OFF_INV >> 2) + lrow]   = inv;
            smf[(OFF_SROW >> 2) + lrow]  = sv;
        }
    }
    grid_sync(0);

    // ============ PHASE 1.5: build g_Bh[b][f][k0..k0+128) (fp16, f-major) ====
    {
        float* xt = smf + (OFF_DYN >> 2);          // [128][65]
        float* sk = xt + 128 * 65;                 // [128]
        const int k0 = blockIdx.x * 128;
        const float* xs = x + ((size_t)b * NN + k0) * FDIM;
#pragma unroll
        for (int q = 0; q < 4; q++) {
            int e = tid + q * 512;                 // 2048 float4
            int row = e >> 4, c4 = (e & 15) * 4;
            float4 v = *(const float4*)&xs[(size_t)row * FDIM + c4];
            xt[row * 65 + c4] = v.x;  xt[row * 65 + c4 + 1] = v.y;
            xt[row * 65 + c4 + 2] = v.z; xt[row * 65 + c4 + 3] = v.w;
        }
        if (tid < 128) sk[tid] = g_s[b * NN + k0 + tid];
        __syncthreads();
        uint32_t* dst = (uint32_t*)(g_Bh + (size_t)b * 128 * NN + k0);
#pragma unroll
        for (int q = 0; q < 16; q++) {
            int e = tid + q * 512;                 // 8192 half2
            int f = e >> 6, kp = e & 63;
            float v0, v1;
            if (f < 64) {
                v0 = xt[(2 * kp) * 65 + f];
                v1 = xt[(2 * kp + 1) * 65 + f];
            } else {
                v0 = sk[2 * kp] * xt[(2 * kp) * 65 + f - 64];
                v1 = sk[2 * kp + 1] * xt[(2 * kp + 1) * 65 + f - 64];
            }
            dst[(size_t)f * (NN / 2) + kp] = h2pack(v0, v1);
        }
    }
    grid_sync(1);

    // ================= PHASE 2: warp-specialized fp16 GEMMs ==================
    if (wid >= 8) {
        // ---------------- PRODUCER ----------------
        const int ptid = tid - 256;
        const int arow = ptid >> 3;
        const int acol = (ptid & 7) * 4;
        const int bf   = ptid >> 1;
        const int bch  = (ptid & 1) * 2;
        const float* gA = Ab + (size_t)(row0 + arow) * NN + acol;
        const __half* gB = Bb + (size_t)bf * NN;

        for (int it = 0; it < NITER; ++it) {
            const int s = it % 3;
            const int k0 = it * KC;
            if (it >= 3) bar_sync512(4 + s);
            float4 va[4];
#pragma unroll
            for (int q = 0; q < 4; q++)
                va[q] = *(const float4*)(gA + k0 + (size_t)q * 32 * NN);
            uint32_t sBb = sb + OFF_STAGE(s) + ASTG_B;
#pragma unroll
            for (int q = 0; q < 2; q++)
                cp_async16(sBb + bf * 80 + (bch + q) * 16,
                           gB + k0 + (bch + q) * 8);
            CP_COMMIT();
            char* dA = smc + OFF_STAGE(s);
#pragma unroll
            for (int q = 0; q < 4; q++) {
                uint2 w;
                w.x = h2pack(va[q].x, va[q].y);
                w.y = h2pack(va[q].z, va[q].w);
                *(uint2*)(dA + (arow + 32 * q) * 80 + acol * 2) = w;
            }
            CP_WAIT0();
            MEMBAR_CTA();
            bar_arrive512(1 + s);
        }
        // stage KmatT fp16 [n:128][k:192]
        {
            uint32_t* km = (uint32_t*)(smc + OFF_KM);
#pragma unroll 1
            for (int e = ptid; e < 128 * 96; e += 256) {
                int n = e / 96;
                int kp = e - n * 96;
                float v0 = __ldg(&Kmat[(size_t)(2 * kp) * 128 + n]);
                float v1 = __ldg(&Kmat[(size_t)(2 * kp + 1) * 128 + n]);
                km[n * KM_STRH + kp] = h2pack(v0, v1);
            }
        }
    } else {
        // ---------------- CONSUMER ----------------
        const int m_base = (wid >> 2) * 64;
        const int n_base = (wid & 3) * 32;
        const bool scaled = (n_base >= 64);
        const int f_base = scaled ? n_base - 64 : n_base;

        float acc[4][4][4];
#pragma unroll
        for (int mt = 0; mt < 4; mt++)
#pragma unroll
            for (int nt = 0; nt < 4; nt++)
#pragma unroll
                for (int q = 0; q < 4; q++) acc[mt][nt][q] = 0.f;

        for (int it = 0; it < NITER; ++it) {
            const int s = it % 3;
            bar_sync512(1 + s);
            const uint32_t* sA = (const uint32_t*)(smc + OFF_STAGE(s));
            const uint32_t* sB = (const uint32_t*)(smc + OFF_STAGE(s) + ASTG_B);
#pragma unroll
            for (int ks = 0; ks < 2; ks++) {
                const int kb = ks * 8;
                uint32_t af[4][4], bf2[4][2];
#pragma unroll
                for (int mt = 0; mt < 4; mt++) {
                    const uint32_t* p = sA + (m_base + mt * 16 + lr) * SA_STRH + kb + lc;
                    af[mt][0] = p[0];
                    af[mt][1] = p[8 * SA_STRH];
                    af[mt][2] = p[4];
                    af[mt][3] = p[8 * SA_STRH + 4];
                }
#pragma unroll
                for (int nt = 0; nt < 4; nt++) {
                    const uint32_t* p = sB + (n_base + nt * 8 + lr) * SB_STRH + kb + lc;
                    bf2[nt][0] = p[0];
                    bf2[nt][1] = p[4];
                }
#pragma unroll
                for (int mt = 0; mt < 4; mt++)
#pragma unroll
                    for (int nt = 0; nt < 4; nt++)
                        mma_f16(acc[mt][nt], af[mt], bf2[nt]);
            }
            bar_arrive512(4 + s);
        }
        bar_sync_n(7, 256);

        // epilogue 1 -> ocat fp16 [128][192]
        uint32_t* oc = (uint32_t*)(smc + OFF_OC);
#pragma unroll
        for (int mt = 0; mt < 4; mt++) {
#pragma unroll
            for (int nt = 0; nt < 4; nt++) {
                const int f = f_base + nt * 8 + lc * 2;
#pragma unroll
                for (int h = 0; h < 2; h++) {
                    const int r = m_base + mt * 16 + lr + h * 8;
                    const float ad = smf[(OFF_ADIAG >> 2) + r];
                    const float c0 = acc[mt][nt][h * 2 + 0];
                    const float c1 = acc[mt][nt][h * 2 + 1];
                    float2 xv = *(const float2*)&xb[(size_t)(row0 + r) * FDIM + f];
                    if (!scaled) {
                        const float inv = smf[(OFF_INV >> 2) + r];
                        float xhx = h2f_rn(xv.x), xhy = h2f_rn(xv.y);
                        float o1a = c0 - ad * xhx;
                        float o1b = c1 - ad * xhy;
                        oc[r * OC_STRH + (f >> 1)] = h2pack(o1a, o1b);
                        oc[r * OC_STRH + ((64 + f) >> 1)] =
                            h2pack(inv * (o1a + xv.x), inv * (o1b + xv.y));
                    } else {
                        const float sv = smf[(OFF_SROW >> 2) + r];
                        float sxx = h2f_rn(sv * xv.x), sxy = h2f_rn(sv * xv.y);
                        float o3a = sv * c0 - sv * ad * sxx + sv * sv * xv.x;
                        float o3b = sv * c1 - sv * ad * sxy + sv * sv * xv.y;
                        oc[r * OC_STRH + ((128 + f) >> 1)] = h2pack(o3a, o3b);
                    }
                }
            }
        }
    }
    __syncthreads();

    // ---- GEMM2: out[128,128] = ocat[128,192] @ KmatT^T  (fp16, 12 k-steps)
    const int mm = (wid >> 2) * 32;
    const int n4 = (wid & 3) * 32;
    const uint32_t* ocp = (const uint32_t*)(smc + OFF_OC);
    const uint32_t* kmp = (const uint32_t*)(smc + OFF_KM);
    float acc2[2][4][4];
#pragma unroll
    for (int mt = 0; mt < 2; mt++)
#pragma unroll
        for (int nt = 0; nt < 4; nt++)
#pragma unroll
            for (int q = 0; q < 4; q++) acc2[mt][nt][q] = 0.f;

#pragma unroll
    for (int ks = 0; ks < 12; ks++) {
        const int kb = ks * 8;
        uint32_t af[2][4], bf2[4][2];
#pragma unroll
        for (int mt = 0; mt < 2; mt++) {
            const uint32_t* p = ocp + (mm + mt * 16 + lr) * OC_STRH + kb + lc;
            af[mt][0] = p[0];
            af[mt][1] = p[8 * OC_STRH];
            af[mt][2] = p[4];
            af[mt][3] = p[8 * OC_STRH + 4];
        }
#pragma unroll
        for (int nt = 0; nt < 4; nt++) {
            const uint32_t* p = kmp + (n4 + nt * 8 + lr) * KM_STRH + kb + lc;
            bf2[nt][0] = p[0];
            bf2[nt][1] = p[4];
        }
#pragma unroll
        for (int mt = 0; mt < 2; mt++)
#pragma unroll
            for (int nt = 0; nt < 4; nt++)
                mma_f16(acc2[mt][nt], af[mt], bf2[nt]);
    }

    // ---- bias + relu + store
#pragma unroll
    for (int mt = 0; mt < 2; mt++) {
#pragma unroll
        for (int nt = 0; nt < 4; nt++) {
            const int col = n4 + nt * 8 + lc * 2;
            float2 bv = *(const float2*)&bias[col];
#pragma unroll
            for (int h = 0; h < 2; h++) {
                const int r = mm + mt * 16 + lr + h * 8;
                float2 o;
                o.x = fmaxf(acc2[mt][nt][h * 2 + 0] + bv.x, 0.f);
                o.y = fmaxf(acc2[mt][nt][h * 2 + 1] + bv.y, 0.f);
                *(float2*)&out[((size_t)b * NN + row0 + r) * OUTD + col] = o;
            }
        }
    }
}

// ---------------------------------------------------------------------------
extern "C" void kernel_launch(void* const* d_in, const int* in_sizes, int n_in,
                              void* d_out, int out_size) {
    const float *x = nullptr, *A = nullptr, *Kmat = nullptr, *bias = nullptr;
    for (int i = 0; i < n_in; i++) {
        switch (in_sizes[i]) {
            case B_ * NN * FDIM:  x    = (const float*)d_in[i]; break;
            case B_ * NN * NN:    A    = (const float*)d_in[i]; break;
            case 3 * FDIM * OUTD: Kmat = (const float*)d_in[i]; break;
            case OUTD:            bias = (const float*)d_in[i]; break;
        }
    }
    float* out = (float*)d_out;

    static bool attr_set = false;
    if (!attr_set) {
        cudaFuncSetAttribute(mega_kernel,
                             cudaFuncAttributeMaxDynamicSharedMemorySize, SMEM_BYTES);
        attr_set = true;
    }

    reset_kernel<<<1, 1>>>();
    mega_kernel<<<dim3(NN / 128, B_), 512, SMEM_BYTES>>>(A, x, Kmat, bias, out);
}